// round 15
// baseline (speedup 1.0000x reference)
#include <cuda_runtime.h>
#include <cuda_fp16.h>
#include <math.h>

#define EDIM 256
#define TM 64
#define XW 132      // u32 words per P/Q row (264 halves); banks 4g+t -> conflict-free
#define BW 264      // u32 words per B kp-row; banks 8t+g -> conflict-free
#define BCH (16*BW) // words per B chunk buffer

typedef unsigned int u32;

// ---------------- device-global scratch (allocation-free workaround) --------
__device__ float g_enc1[EDIM*EDIM], g_enc2[EDIM*EDIM];
__device__ float g_aff_a[EDIM*EDIM], g_aff_v[EDIM*EDIM];
__device__ float g_A1[EDIM*EDIM],  g_A2[EDIM*EDIM];
// fp16 pair-interleaved weights: g_wp[z][kp*256 + n] = half2{W[n][2kp], W[n][2kp+1]}
// z: 0=wca 1=wha 2=wcv 3=whv 4=fc1a 5=fc1b
__device__ u32 g_wp[6][128*256];

// ---------------- fp16 tensor-core mma (m16n8k16, fp32 accum) ---------------
__device__ __forceinline__ void hmma(float* c, u32 a0, u32 a1, u32 a2, u32 a3,
                                     u32 b0, u32 b1) {
    asm("mma.sync.aligned.m16n8k16.row.col.f32.f16.f16.f32 "
        "{%0,%1,%2,%3}, {%4,%5,%6,%7}, {%8,%9}, {%0,%1,%2,%3};"
        : "+f"(c[0]), "+f"(c[1]), "+f"(c[2]), "+f"(c[3])
        : "r"(a0), "r"(a1), "r"(a2), "r"(a3), "r"(b0), "r"(b1));
}
__device__ __forceinline__ u32 packh2(float x, float y) {
    __half2 h = __floats2half2_rn(x, y);
    return *(u32*)&h;
}

// ---------------- prologue GEMM body: C = A @ B^T (+bias), scalar (KNOWN GOOD)
__device__ __forceinline__ void gemm_body_s(const float* __restrict__ A,
                                            const float* __restrict__ B,
                                            const float* __restrict__ bias,
                                            float* __restrict__ C, int K) {
    __shared__ float As[16][17], Bs[16][17];
    int tx = threadIdx.x, ty = threadIdx.y;
    int row = blockIdx.y * 16 + ty;
    int col = blockIdx.x * 16 + tx;
    float acc = 0.f;
    for (int k0 = 0; k0 < K; k0 += 16) {
        As[ty][tx] = A[row * K + k0 + tx];
        Bs[ty][tx] = B[(blockIdx.x * 16 + ty) * K + k0 + tx];
        __syncthreads();
#pragma unroll
        for (int kk = 0; kk < 16; kk++) acc = fmaf(As[ty][kk], Bs[tx][kk], acc);
        __syncthreads();
    }
    C[row * 256 + col] = acc + (bias ? bias[col] : 0.f);
}

__global__ void enc_gemms(const float* __restrict__ f1, const float* __restrict__ f2,
                          const float* __restrict__ w1, const float* __restrict__ b1,
                          const float* __restrict__ w2, const float* __restrict__ b2) {
    if (blockIdx.z == 0) gemm_body_s(f1, w1, b1, g_enc1, 768);
    else                 gemm_body_s(f2, w2, b2, g_enc2, 768);
}
__global__ void quad_gemms(const float* __restrict__ affa, const float* __restrict__ affv,
                           const float* __restrict__ wa,   const float* __restrict__ wv) {
    switch (blockIdx.z) {
        case 0: gemm_body_s(g_enc1, affa, nullptr, g_aff_a, 256); break;
        case 1: gemm_body_s(g_enc2, affv, nullptr, g_aff_v, 256); break;
        case 2: gemm_body_s(g_enc1, wa,   nullptr, g_A1,    256); break;
        default: gemm_body_s(g_enc2, wv,  nullptr, g_A2,    256); break;
    }
}

// pack weights to fp16 pair-interleaved k-major layout
__global__ void pack_weights(const float* __restrict__ wca, const float* __restrict__ wha,
                             const float* __restrict__ wcv, const float* __restrict__ whv,
                             const float* __restrict__ fc1) {
    int z = blockIdx.z;
    const float* src; int ldk, co;
    switch (z) {
        case 0: src = wca; ldk = 256; co = 0;   break;
        case 1: src = wha; ldk = 256; co = 0;   break;
        case 2: src = wcv; ldk = 256; co = 0;   break;
        case 3: src = whv; ldk = 256; co = 0;   break;
        case 4: src = fc1; ldk = 512; co = 0;   break;
        default: src = fc1; ldk = 512; co = 256; break;
    }
    int kp = blockIdx.y;            // 0..127
    int n  = threadIdx.x;           // 0..255
    float2 w = *(const float2*)&src[n * ldk + co + 2 * kp];
    g_wp[z][kp * 256 + n] = packh2(w.x, w.y);
}

// ---------------- fused chain: fp16 mma, 16 warps (2 row x 8 col, 32x32/warp)
// One GEMM pass: acc[8][4] += A(64x256 fp16 in smem) @ W^T (streamed fp16).
// Double buffer, ONE barrier per 32-k chunk (discipline proven in R9/R11/R14).
__device__ __forceinline__ void run_pass(const u32* __restrict__ gw,
                                         u32* __restrict__ sB,
                                         const u32* __restrict__ Aw,
                                         float (*acc)[4], int tid) {
    const int lane = tid & 31, wid = tid >> 5;
    const int wr = wid & 1, wc = wid >> 1;        // 2 row-warps x 8 col-warps
    const int g = lane >> 2, t = lane & 3;
    const int mr = wr * 32, nc = wc * 32;
    const int sn = tid & 255, sk = (tid >> 8) * 8;   // staging: 8 rows, col sn

    // stage chunk 0 (kp rows 0..15)
#pragma unroll
    for (int kpl = 0; kpl < 8; kpl++)
        sB[(sk + kpl) * BW + sn] = gw[(sk + kpl) * 256 + sn];
    __syncthreads();

#pragma unroll 1
    for (int c = 0; c < 8; c++) {
        u32 v[8];
        const bool more = c < 7;
        if (more) {
#pragma unroll
            for (int kpl = 0; kpl < 8; kpl++)
                v[kpl] = gw[((c + 1) * 16 + sk + kpl) * 256 + sn];
        }
        const u32* Bb = sB + (c & 1) * BCH;
#pragma unroll
        for (int s = 0; s < 2; s++) {
            const int kw = c * 16 + s * 8;       // word offset into A row
            u32 a[2][4];
#pragma unroll
            for (int mt = 0; mt < 2; mt++) {
                const u32* Ar = Aw + (mr + mt * 16 + g) * XW + kw + t;
                a[mt][0] = Ar[0];
                a[mt][1] = Ar[8 * XW];
                a[mt][2] = Ar[4];
                a[mt][3] = Ar[8 * XW + 4];
            }
#pragma unroll
            for (int nt = 0; nt < 4; nt++) {
                const int n = nc + nt * 8 + g;
                u32 b0 = Bb[(s * 8 + t) * BW + n];
                u32 b1 = Bb[(s * 8 + 4 + t) * BW + n];
                hmma(acc[nt],     a[0][0], a[0][1], a[0][2], a[0][3], b0, b1);
                hmma(acc[4 + nt], a[1][0], a[1][1], a[1][2], a[1][3], b0, b1);
            }
        }
        if (more) {
            u32* d = sB + ((c + 1) & 1) * BCH;
#pragma unroll
            for (int kpl = 0; kpl < 8; kpl++)
                d[(sk + kpl) * BW + sn] = v[kpl];
        }
        __syncthreads();
    }
}

// epilogue: dst[r][j] = act(acc + gAdd[r*256+j]) as fp16 into smem (word layout XW)
__device__ __forceinline__ void epi_store(float (*acc)[4], const float* __restrict__ gAdd,
                                          u32* __restrict__ dstw, bool do_relu, int tid) {
    const int lane = tid & 31, wid = tid >> 5;
    const int wr = wid & 1, wc = wid >> 1;
    const int g = lane >> 2, t = lane & 3;
    const int mr = wr * 32, nc = wc * 32;
#pragma unroll
    for (int mt = 0; mt < 2; mt++)
#pragma unroll
        for (int nt = 0; nt < 4; nt++) {
            const int j0 = nc + nt * 8 + 2 * t;
            const int r1 = mr + mt * 16 + g;
            float* a = acc[mt * 4 + nt];
            float2 g0 = *(const float2*)&gAdd[r1 * 256 + j0];
            float2 g1 = *(const float2*)&gAdd[(r1 + 8) * 256 + j0];
            float v0 = a[0] + g0.x, v1 = a[1] + g0.y;
            float v2 = a[2] + g1.x, v3 = a[3] + g1.y;
            if (do_relu) {
                v0 = fmaxf(v0, 0.f); v1 = fmaxf(v1, 0.f);
                v2 = fmaxf(v2, 0.f); v3 = fmaxf(v3, 0.f);
            }
            const int cw = wc * 16 + nt * 4 + t;
            dstw[r1 * XW + cw]       = packh2(v0, v1);
            dstw[(r1 + 8) * XW + cw] = packh2(v2, v3);
        }
    __syncthreads();
}

#define SMEM_WORDS (3 * 8448 + 4 * 256 + 512 + 2 * 64)
#define SMEM_BYTES (SMEM_WORDS * 4)

__global__ __launch_bounds__(512, 1)
void fused_hmma(const float* __restrict__ fc1_b, const float* __restrict__ fc2_w,
                const float* __restrict__ fc2_b, float* __restrict__ out) {
    extern __shared__ u32 usm[];
    u32* uP   = usm;                    // [64][XW]
    u32* uQ   = uP + 8448;              // [64][XW]
    u32* uB   = uQ + 8448;              // 2 x [16][BW]
    float* fAffA = (float*)(uB + 8448);
    float* fAffV = fAffA + 256;
    float* fFb   = fAffV + 256;
    float* fF2   = fFb + 256;
    float* fRed  = fF2 + 256;           // [8][64]
    float* fE1   = fRed + 512;
    float* fE2   = fE1 + 64;

    const int tid = threadIdx.x;
    const int b   = blockIdx.y;
    const int r0  = blockIdx.x * TM;
    const float scale = 0.0625f;        // 1/sqrt(256)

    if (tid < 256) {
        fAffA[tid] = g_aff_a[b * 256 + tid];
        fAffV[tid] = g_aff_v[b * 256 + tid];
        fFb[tid]   = fc1_b[tid];
        fF2[tid]   = fc2_w[tid];
    }
    if (tid < TM) {
        fE1[tid] = g_enc1[b * 256 + r0 + tid];
        fE2[tid] = g_enc2[b * 256 + r0 + tid];
    }
    const float fc2b0 = fc2_b[0];
    __syncthreads();

    float acc[8][4];

    // ---- attn_a -> P (fp16) ----
    for (int idx = tid; idx < TM * 128; idx += 512) {
        int i = idx >> 7, jp = idx & 127;
        float ev = fE1[i];
        uP[i * XW + jp] = packh2(tanhf(ev * fAffA[2 * jp] * scale),
                                 tanhf(ev * fAffA[2 * jp + 1] * scale));
    }
    __syncthreads();

    // ---- GEMM1: H_a = relu(attn_a @ wca^T + A1) -> Q ----
#pragma unroll
    for (int i = 0; i < 8; i++)
#pragma unroll
        for (int e = 0; e < 4; e++) acc[i][e] = 0.f;
    run_pass(g_wp[0], uB, uP, acc, tid);
    epi_store(acc, g_A1 + r0 * 256, uQ, true, tid);

    // ---- GEMM2: ae1 = H_a @ wha^T + enc1 -> P ----
#pragma unroll
    for (int i = 0; i < 8; i++)
#pragma unroll
        for (int e = 0; e < 4; e++) acc[i][e] = 0.f;
    run_pass(g_wp[1], uB, uQ, acc, tid);
    epi_store(acc, g_enc1 + r0 * 256, uP, false, tid);

    // ---- attn_v -> Q ----
    for (int idx = tid; idx < TM * 128; idx += 512) {
        int i = idx >> 7, jp = idx & 127;
        float ev = fE2[i];
        uQ[i * XW + jp] = packh2(tanhf(ev * fAffV[2 * jp] * scale),
                                 tanhf(ev * fAffV[2 * jp + 1] * scale));
    }
    __syncthreads();

    // ---- GEMM3: H_v = relu(attn_v @ wcv^T + A2) -> Q (in place) ----
#pragma unroll
    for (int i = 0; i < 8; i++)
#pragma unroll
        for (int e = 0; e < 4; e++) acc[i][e] = 0.f;
    run_pass(g_wp[2], uB, uQ, acc, tid);
    epi_store(acc, g_A2 + r0 * 256, uQ, true, tid);

    // ---- GEMM4: ae2 = H_v @ whv^T + enc2 -> Q (in place) ----
#pragma unroll
    for (int i = 0; i < 8; i++)
#pragma unroll
        for (int e = 0; e < 4; e++) acc[i][e] = 0.f;
    run_pass(g_wp[3], uB, uQ, acc, tid);
    epi_store(acc, g_enc2 + r0 * 256, uQ, false, tid);

    // ---- fc1: h = relu(ae1 @ fc1a^T + ae2 @ fc1b^T + b1) ----
#pragma unroll
    for (int i = 0; i < 8; i++)
#pragma unroll
        for (int e = 0; e < 4; e++) acc[i][e] = 0.f;
    run_pass(g_wp[4], uB, uP, acc, tid);
    run_pass(g_wp[5], uB, uQ, acc, tid);

    // ---- final: out = relu(h) . fc2 + b2 ----
    {
        const int lane = tid & 31, wid = tid >> 5;
        const int wr = wid & 1, wc = wid >> 1;
        const int g = lane >> 2, t = lane & 3;
        const int mr = wr * 32, nc = wc * 32;
        float rp[4] = {0.f, 0.f, 0.f, 0.f};
#pragma unroll
        for (int mt = 0; mt < 2; mt++)
#pragma unroll
            for (int nt = 0; nt < 4; nt++) {
                const int j0 = nc + nt * 8 + 2 * t;
                float* a = acc[mt * 4 + nt];
                float fb0 = fFb[j0], fb1 = fFb[j0 + 1];
                float f20 = fF2[j0], f21 = fF2[j0 + 1];
                rp[mt * 2]     += fmaxf(a[0] + fb0, 0.f) * f20 + fmaxf(a[1] + fb1, 0.f) * f21;
                rp[mt * 2 + 1] += fmaxf(a[2] + fb0, 0.f) * f20 + fmaxf(a[3] + fb1, 0.f) * f21;
            }
#pragma unroll
        for (int r = 0; r < 4; r++) {
            rp[r] += __shfl_xor_sync(0xffffffffu, rp[r], 1);
            rp[r] += __shfl_xor_sync(0xffffffffu, rp[r], 2);
        }
        if (t == 0) {
#pragma unroll
            for (int mt = 0; mt < 2; mt++) {
                fRed[wc * 64 + mr + mt * 16 + g]     = rp[mt * 2];
                fRed[wc * 64 + mr + mt * 16 + g + 8] = rp[mt * 2 + 1];
            }
        }
    }
    __syncthreads();
    if (tid < TM) {
        float s = fc2b0;
#pragma unroll
        for (int w8 = 0; w8 < 8; w8++) s += fRed[w8 * 64 + tid];
        out[b * 256 + r0 + tid] = s;
    }
}

// ---------------- launch --------------------------------------------------
extern "C" void kernel_launch(void* const* d_in, const int* in_sizes, int n_in,
                              void* d_out, int out_size) {
    const float* features1 = (const float*)d_in[0];
    const float* features2 = (const float*)d_in[1];
    const float* enc1_w = (const float*)d_in[2];
    const float* enc1_b = (const float*)d_in[3];
    const float* enc2_w = (const float*)d_in[4];
    const float* enc2_b = (const float*)d_in[5];
    const float* affa_w = (const float*)d_in[6];
    const float* affv_w = (const float*)d_in[7];
    const float* wa_w   = (const float*)d_in[8];
    const float* wv_w   = (const float*)d_in[9];
    const float* wca_w  = (const float*)d_in[10];
    const float* wcv_w  = (const float*)d_in[11];
    const float* wha_w  = (const float*)d_in[12];
    const float* whv_w  = (const float*)d_in[13];
    const float* fc1_w  = (const float*)d_in[14];
    const float* fc1_b  = (const float*)d_in[15];
    const float* fc2_w  = (const float*)d_in[16];
    const float* fc2_b  = (const float*)d_in[17];
    float* out = (float*)d_out;

    cudaFuncSetAttribute(fused_hmma, cudaFuncAttributeMaxDynamicSharedMemorySize,
                         SMEM_BYTES);

    pack_weights<<<dim3(1, 128, 6), 256>>>(wca_w, wha_w, wcv_w, whv_w, fc1_w);
    enc_gemms<<<dim3(16, 16, 2), dim3(16, 16)>>>(features1, features2,
                                                 enc1_w, enc1_b, enc2_w, enc2_b);
    quad_gemms<<<dim3(16, 16, 4), dim3(16, 16)>>>(affa_w, affv_w, wa_w, wv_w);

    fused_hmma<<<dim3(256 / TM, 256), 512, SMEM_BYTES>>>(fc1_b, fc2_w, fc2_b, out);
}

// round 16
// speedup vs baseline: 1.2097x; 1.2097x over previous
#include <cuda_runtime.h>
#include <cuda_fp16.h>
#include <math.h>

#define EDIM 256
#define TM 64
#define XW 132      // u32 words per P/Q row (264 halves); ldmatrix rows banks 4r -> conflict-free
#define KW 36       // u32 words per B smem row (32 data + 4 pad); banks 4n -> conflict-free
#define BCHW (256*KW)   // words per B chunk buffer (one 64-k chunk, all 256 n)

typedef unsigned int u32;

// ---------------- device-global scratch (allocation-free workaround) --------
__device__ float g_enc1[EDIM*EDIM], g_enc2[EDIM*EDIM];
__device__ float g_aff_a[EDIM*EDIM], g_aff_v[EDIM*EDIM];
__device__ float g_A1[EDIM*EDIM],  g_A2[EDIM*EDIM];
// fp16 pair-interleaved weights, N-MAJOR: g_wp[z][n*128 + kp] = half2{W[n][2kp], W[n][2kp+1]}
// z: 0=wca 1=wha 2=wcv 3=whv 4=fc1a 5=fc1b
__device__ u32 g_wp[6][256*128];

// ---------------- mma / ldmatrix / cp.async helpers -------------------------
__device__ __forceinline__ void hmma(float* c, u32 a0, u32 a1, u32 a2, u32 a3,
                                     u32 b0, u32 b1) {
    asm("mma.sync.aligned.m16n8k16.row.col.f32.f16.f16.f32 "
        "{%0,%1,%2,%3}, {%4,%5,%6,%7}, {%8,%9}, {%0,%1,%2,%3};"
        : "+f"(c[0]), "+f"(c[1]), "+f"(c[2]), "+f"(c[3])
        : "r"(a0), "r"(a1), "r"(a2), "r"(a3), "r"(b0), "r"(b1));
}
__device__ __forceinline__ void ldsm4(u32& r0, u32& r1, u32& r2, u32& r3, u32 addr) {
    asm volatile("ldmatrix.sync.aligned.m8n8.x4.shared.b16 {%0,%1,%2,%3}, [%4];"
                 : "=r"(r0), "=r"(r1), "=r"(r2), "=r"(r3) : "r"(addr));
}
__device__ __forceinline__ u32 packh2(float x, float y) {
    __half2 h = __floats2half2_rn(x, y);
    return *(u32*)&h;
}
__device__ __forceinline__ u32 smem_addr(const void* p) {
    return (u32)__cvta_generic_to_shared(p);
}
#define CP_ASYNC16(dst, src) \
    asm volatile("cp.async.ca.shared.global [%0], [%1], 16;" :: "r"(dst), "l"(src))
#define CP_COMMIT() asm volatile("cp.async.commit_group;")
#define CP_WAIT0()  asm volatile("cp.async.wait_group 0;")

// ---------------- prologue GEMM body: C = A @ B^T (+bias), scalar (KNOWN GOOD)
__device__ __forceinline__ void gemm_body_s(const float* __restrict__ A,
                                            const float* __restrict__ B,
                                            const float* __restrict__ bias,
                                            float* __restrict__ C, int K) {
    __shared__ float As[16][17], Bs[16][17];
    int tx = threadIdx.x, ty = threadIdx.y;
    int row = blockIdx.y * 16 + ty;
    int col = blockIdx.x * 16 + tx;
    float acc = 0.f;
    for (int k0 = 0; k0 < K; k0 += 16) {
        As[ty][tx] = A[row * K + k0 + tx];
        Bs[ty][tx] = B[(blockIdx.x * 16 + ty) * K + k0 + tx];
        __syncthreads();
#pragma unroll
        for (int kk = 0; kk < 16; kk++) acc = fmaf(As[ty][kk], Bs[tx][kk], acc);
        __syncthreads();
    }
    C[row * 256 + col] = acc + (bias ? bias[col] : 0.f);
}

__global__ void enc_gemms(const float* __restrict__ f1, const float* __restrict__ f2,
                          const float* __restrict__ w1, const float* __restrict__ b1,
                          const float* __restrict__ w2, const float* __restrict__ b2) {
    if (blockIdx.z == 0) gemm_body_s(f1, w1, b1, g_enc1, 768);
    else                 gemm_body_s(f2, w2, b2, g_enc2, 768);
}
__global__ void quad_gemms(const float* __restrict__ affa, const float* __restrict__ affv,
                           const float* __restrict__ wa,   const float* __restrict__ wv) {
    switch (blockIdx.z) {
        case 0: gemm_body_s(g_enc1, affa, nullptr, g_aff_a, 256); break;
        case 1: gemm_body_s(g_enc2, affv, nullptr, g_aff_v, 256); break;
        case 2: gemm_body_s(g_enc1, wa,   nullptr, g_A1,    256); break;
        default: gemm_body_s(g_enc2, wv,  nullptr, g_A2,    256); break;
    }
}

// pack weights to fp16 pair-interleaved N-MAJOR layout
__global__ void pack_weights(const float* __restrict__ wca, const float* __restrict__ wha,
                             const float* __restrict__ wcv, const float* __restrict__ whv,
                             const float* __restrict__ fc1) {
    int z = blockIdx.z;
    const float* src; int ldk, co;
    switch (z) {
        case 0: src = wca; ldk = 256; co = 0;   break;
        case 1: src = wha; ldk = 256; co = 0;   break;
        case 2: src = wcv; ldk = 256; co = 0;   break;
        case 3: src = whv; ldk = 256; co = 0;   break;
        case 4: src = fc1; ldk = 512; co = 0;   break;
        default: src = fc1; ldk = 512; co = 256; break;
    }
    int kp = blockIdx.y;            // 0..127
    int n  = threadIdx.x;           // 0..255
    float2 w = *(const float2*)&src[n * ldk + co + 2 * kp];
    g_wp[z][n * 128 + kp] = packh2(w.x, w.y);
}

// ---------------- fused chain: fp16 mma + ldmatrix + cp.async ---------------
// 8 warps (2 row x 4 col), 32x64 per-warp tile (R14 shape). 64-k chunks, 4/pass.

// stage one 64-k chunk (32 words per n) via cp.async into padded [256][KW]
__device__ __forceinline__ void stage_cp(const u32* __restrict__ gw, u32 sB_addr,
                                         int c, int buf, int tid) {
    const int seg = tid & 7, n0 = tid >> 3;       // 32 n rows per sweep
    const u32* src = gw + n0 * 128 + c * 32 + seg * 4;
    u32 dst = sB_addr + (u32)((buf * BCHW + n0 * KW + seg * 4) * 4);
#pragma unroll
    for (int it = 0; it < 8; it++) {
        CP_ASYNC16(dst, src);
        src += 32 * 128;
        dst += 32 * KW * 4;
    }
    CP_COMMIT();
}

__device__ __forceinline__ void run_pass(const u32* __restrict__ gw,
                                         u32 sB_addr, u32 A_addr,
                                         float (*acc)[4], int tid) {
    const int lane = tid & 31, wid = tid >> 5;
    const int wr = wid & 1, wc = wid >> 1;        // 2 row-warps x 4 col-warps
    const int mr = wr * 32, nc = wc * 64;

    // ldmatrix lane-address components
    const int arow = mr + (lane & 15);
    const u32 aA0 = A_addr + (u32)((arow * XW + (lane >> 4) * 4) * 4);  // mt=0
    const u32 aA1 = aA0 + (u32)(16 * XW * 4);                            // mt=1
    const int nOff = ((lane >> 4) << 3) + (lane & 7);
    const int kOff = ((lane >> 3) & 1) * 4;

    stage_cp(gw, sB_addr, 0, 0, tid);

#pragma unroll 1
    for (int c = 0; c < 4; c++) {
        CP_WAIT0();
        __syncthreads();                 // chunk c visible; safe to overwrite buf (c+1)&1
        if (c < 3) stage_cp(gw, sB_addr, c + 1, (c + 1) & 1, tid);

        const u32 bB = sB_addr + (u32)((c & 1) * BCHW * 4);
#pragma unroll
        for (int q = 0; q < 4; q++) {    // k16 subtiles within 64-k chunk
            const u32 kb = (u32)((c * 32 + q * 8) * 4);   // byte offset into A row
            u32 a0[4], a1[4];
            ldsm4(a0[0], a0[1], a0[2], a0[3], aA0 + kb);
            ldsm4(a1[0], a1[1], a1[2], a1[3], aA1 + kb);
#pragma unroll
            for (int p = 0; p < 4; p++) { // pairs of 8-wide n tiles
                u32 b0, b1, b2, b3;
                const int n = nc + p * 16 + nOff;
                ldsm4(b0, b1, b2, b3, bB + (u32)((n * KW + q * 8 + kOff) * 4));
                hmma(acc[2 * p],     a0[0], a0[1], a0[2], a0[3], b0, b1);
                hmma(acc[2 * p + 1], a0[0], a0[1], a0[2], a0[3], b2, b3);
                hmma(acc[8 + 2 * p],     a1[0], a1[1], a1[2], a1[3], b0, b1);
                hmma(acc[8 + 2 * p + 1], a1[0], a1[1], a1[2], a1[3], b2, b3);
            }
        }
    }
    __syncthreads();
}

// epilogue: dst[r][j] = act(acc + gAdd[r*256+j]) as fp16 into smem (word layout XW)
__device__ __forceinline__ void epi_store(float (*acc)[4], const float* __restrict__ gAdd,
                                          u32* __restrict__ dstw, bool do_relu, int tid) {
    const int lane = tid & 31, wid = tid >> 5;
    const int wr = wid & 1, wc = wid >> 1;
    const int g = lane >> 2, t = lane & 3;
    const int mr = wr * 32, nc = wc * 64;
#pragma unroll
    for (int mt = 0; mt < 2; mt++)
#pragma unroll
        for (int nt = 0; nt < 8; nt++) {
            const int j0 = nc + nt * 8 + 2 * t;
            const int r1 = mr + mt * 16 + g;
            float* a = acc[mt * 8 + nt];
            float2 g0 = *(const float2*)&gAdd[r1 * 256 + j0];
            float2 g1 = *(const float2*)&gAdd[(r1 + 8) * 256 + j0];
            float v0 = a[0] + g0.x, v1 = a[1] + g0.y;
            float v2 = a[2] + g1.x, v3 = a[3] + g1.y;
            if (do_relu) {
                v0 = fmaxf(v0, 0.f); v1 = fmaxf(v1, 0.f);
                v2 = fmaxf(v2, 0.f); v3 = fmaxf(v3, 0.f);
            }
            const int cw = (nc >> 1) + nt * 4 + t;
            dstw[r1 * XW + cw]       = packh2(v0, v1);
            dstw[(r1 + 8) * XW + cw] = packh2(v2, v3);
        }
    __syncthreads();
}

#define SMEM_WORDS (2 * 8448 + 2 * BCHW + 5 * 256 + 2 * 64)
#define SMEM_BYTES (SMEM_WORDS * 4)

__global__ __launch_bounds__(256, 1)
void fused_hmma(const float* __restrict__ fc1_b, const float* __restrict__ fc2_w,
                const float* __restrict__ fc2_b, float* __restrict__ out) {
    extern __shared__ u32 usm[];
    u32* uP   = usm;                    // [64][XW]
    u32* uQ   = uP + 8448;              // [64][XW]
    u32* uB   = uQ + 8448;              // 2 x [256][KW]
    float* fAffA = (float*)(uB + 2 * BCHW);
    float* fAffV = fAffA + 256;
    float* fFb   = fAffV + 256;
    float* fF2   = fFb + 256;
    float* fRed  = fF2 + 256;           // [4][64]
    float* fE1   = fRed + 256;
    float* fE2   = fE1 + 64;

    const int tid = threadIdx.x;
    const int b   = blockIdx.y;
    const int r0  = blockIdx.x * TM;
    const float scale = 0.0625f;        // 1/sqrt(256)

    const u32 sB_addr = smem_addr(uB);
    const u32 uP_addr = smem_addr(uP);
    const u32 uQ_addr = smem_addr(uQ);

    fAffA[tid] = g_aff_a[b * 256 + tid];
    fAffV[tid] = g_aff_v[b * 256 + tid];
    fFb[tid]   = fc1_b[tid];
    fF2[tid]   = fc2_w[tid];
    if (tid < TM) {
        fE1[tid] = g_enc1[b * 256 + r0 + tid];
        fE2[tid] = g_enc2[b * 256 + r0 + tid];
    }
    const float fc2b0 = fc2_b[0];
    __syncthreads();

    float acc[16][4];

    // ---- attn_a -> P (fp16) ----
    for (int idx = tid; idx < TM * 128; idx += 256) {
        int i = idx >> 7, jp = idx & 127;
        float ev = fE1[i];
        uP[i * XW + jp] = packh2(tanhf(ev * fAffA[2 * jp] * scale),
                                 tanhf(ev * fAffA[2 * jp + 1] * scale));
    }
    __syncthreads();

    // ---- GEMM1: H_a = relu(attn_a @ wca^T + A1) -> Q ----
#pragma unroll
    for (int i = 0; i < 16; i++)
#pragma unroll
        for (int e = 0; e < 4; e++) acc[i][e] = 0.f;
    run_pass(g_wp[0], sB_addr, uP_addr, acc, tid);
    epi_store(acc, g_A1 + r0 * 256, uQ, true, tid);

    // ---- GEMM2: ae1 = H_a @ wha^T + enc1 -> P ----
#pragma unroll
    for (int i = 0; i < 16; i++)
#pragma unroll
        for (int e = 0; e < 4; e++) acc[i][e] = 0.f;
    run_pass(g_wp[1], sB_addr, uQ_addr, acc, tid);
    epi_store(acc, g_enc1 + r0 * 256, uP, false, tid);

    // ---- attn_v -> Q ----
    for (int idx = tid; idx < TM * 128; idx += 256) {
        int i = idx >> 7, jp = idx & 127;
        float ev = fE2[i];
        uQ[i * XW + jp] = packh2(tanhf(ev * fAffV[2 * jp] * scale),
                                 tanhf(ev * fAffV[2 * jp + 1] * scale));
    }
    __syncthreads();

    // ---- GEMM3: H_v = relu(attn_v @ wcv^T + A2) -> Q (in place) ----
#pragma unroll
    for (int i = 0; i < 16; i++)
#pragma unroll
        for (int e = 0; e < 4; e++) acc[i][e] = 0.f;
    run_pass(g_wp[2], sB_addr, uQ_addr, acc, tid);
    epi_store(acc, g_A2 + r0 * 256, uQ, true, tid);

    // ---- GEMM4: ae2 = H_v @ whv^T + enc2 -> Q (in place) ----
#pragma unroll
    for (int i = 0; i < 16; i++)
#pragma unroll
        for (int e = 0; e < 4; e++) acc[i][e] = 0.f;
    run_pass(g_wp[3], sB_addr, uQ_addr, acc, tid);
    epi_store(acc, g_enc2 + r0 * 256, uQ, false, tid);

    // ---- fc1: h = relu(ae1 @ fc1a^T + ae2 @ fc1b^T + b1) ----
#pragma unroll
    for (int i = 0; i < 16; i++)
#pragma unroll
        for (int e = 0; e < 4; e++) acc[i][e] = 0.f;
    run_pass(g_wp[4], sB_addr, uP_addr, acc, tid);
    run_pass(g_wp[5], sB_addr, uQ_addr, acc, tid);

    // ---- final: out = relu(h) . fc2 + b2 ----
    {
        const int lane = tid & 31, wid = tid >> 5;
        const int wr = wid & 1, wc = wid >> 1;
        const int g = lane >> 2, t = lane & 3;
        const int mr = wr * 32, nc = wc * 64;
        float rp[4] = {0.f, 0.f, 0.f, 0.f};
#pragma unroll
        for (int mt = 0; mt < 2; mt++)
#pragma unroll
            for (int nt = 0; nt < 8; nt++) {
                const int j0 = nc + nt * 8 + 2 * t;
                float* a = acc[mt * 8 + nt];
                float fb0 = fFb[j0], fb1 = fFb[j0 + 1];
                float f20 = fF2[j0], f21 = fF2[j0 + 1];
                rp[mt * 2]     += fmaxf(a[0] + fb0, 0.f) * f20 + fmaxf(a[1] + fb1, 0.f) * f21;
                rp[mt * 2 + 1] += fmaxf(a[2] + fb0, 0.f) * f20 + fmaxf(a[3] + fb1, 0.f) * f21;
            }
#pragma unroll
        for (int r = 0; r < 4; r++) {
            rp[r] += __shfl_xor_sync(0xffffffffu, rp[r], 1);
            rp[r] += __shfl_xor_sync(0xffffffffu, rp[r], 2);
        }
        if (t == 0) {
#pragma unroll
            for (int mt = 0; mt < 2; mt++) {
                fRed[wc * 64 + mr + mt * 16 + g]     = rp[mt * 2];
                fRed[wc * 64 + mr + mt * 16 + g + 8] = rp[mt * 2 + 1];
            }
        }
    }
    __syncthreads();
    if (tid < TM) {
        out[b * 256 + r0 + tid] = fRed[tid] + fRed[64 + tid] + fRed[128 + tid]
                                + fRed[192 + tid] + fc2b0;
    }
}

// ---------------- launch --------------------------------------------------
extern "C" void kernel_launch(void* const* d_in, const int* in_sizes, int n_in,
                              void* d_out, int out_size) {
    const float* features1 = (const float*)d_in[0];
    const float* features2 = (const float*)d_in[1];
    const float* enc1_w = (const float*)d_in[2];
    const float* enc1_b = (const float*)d_in[3];
    const float* enc2_w = (const float*)d_in[4];
    const float* enc2_b = (const float*)d_in[5];
    const float* affa_w = (const float*)d_in[6];
    const float* affv_w = (const float*)d_in[7];
    const float* wa_w   = (const float*)d_in[8];
    const float* wv_w   = (const float*)d_in[9];
    const float* wca_w  = (const float*)d_in[10];
    const float* wcv_w  = (const float*)d_in[11];
    const float* wha_w  = (const float*)d_in[12];
    const float* whv_w  = (const float*)d_in[13];
    const float* fc1_w  = (const float*)d_in[14];
    const float* fc1_b  = (const float*)d_in[15];
    const float* fc2_w  = (const float*)d_in[16];
    const float* fc2_b  = (const float*)d_in[17];
    float* out = (float*)d_out;

    cudaFuncSetAttribute(fused_hmma, cudaFuncAttributeMaxDynamicSharedMemorySize,
                         SMEM_BYTES);

    pack_weights<<<dim3(1, 128, 6), 256>>>(wca_w, wha_w, wcv_w, whv_w, fc1_w);
    enc_gemms<<<dim3(16, 16, 2), dim3(16, 16)>>>(features1, features2,
                                                 enc1_w, enc1_b, enc2_w, enc2_b);
    quad_gemms<<<dim3(16, 16, 4), dim3(16, 16)>>>(affa_w, affv_w, wa_w, wv_w);

    fused_hmma<<<dim3(256 / TM, 256), 256, SMEM_BYTES>>>(fc1_b, fc2_w, fc2_b, out);
}